// round 2
// baseline (speedup 1.0000x reference)
#include <cuda_runtime.h>
#include <cuda_bf16.h>
#include <cstdint>

#define N_NODES 50000
#define N_EDGES 600000
#define VOCAB   32000
#define D       128

// Scratch: precomputed per-token transformed embeddings (allowed: __device__ globals)
__device__ float g_T1[(size_t)VOCAB * D];   // relu(emb @ w1 + b1) per token
__device__ float g_T2[(size_t)VOCAB * D];   // relu(emb @ w2 + b2) per token

// ---------------------------------------------------------------------------
// Kernel 1: zero the output (harness poisons it to 0xAA)
// ---------------------------------------------------------------------------
__global__ void zero_kernel(float4* __restrict__ out, int n4) {
    int i = blockIdx.x * blockDim.x + threadIdx.x;
    if (i < n4) out[i] = make_float4(0.f, 0.f, 0.f, 0.f);
}

// ---------------------------------------------------------------------------
// Kernel 2: T = relu(emb @ W + b) for both (w1,b1)->g_T1 and (w2,b2)->g_T2
// blockIdx.y selects which table. Tiled fp32 GEMM:
//   BM=64 rows, BN=128 cols (full), BK=32; 256 threads, each computes 4x8.
// ---------------------------------------------------------------------------
#define BM 64
#define BN 128
#define BK 32
#define TM 4
#define TN 8

__global__ void __launch_bounds__(256) gemm_relu_kernel(
    const float* __restrict__ emb,
    const float* __restrict__ w1, const float* __restrict__ b1,
    const float* __restrict__ w2, const float* __restrict__ b2)
{
    const float* W  = blockIdx.y ? w2 : w1;
    const float* Bv = blockIdx.y ? b2 : b1;
    float* outT     = blockIdx.y ? g_T2 : g_T1;

    __shared__ float As[BK][BM + 1];    // +1 pad: conflict-free transpose store
    __shared__ float Ws[BK][BN + 4];    // +4 pad: conflict-free float4 reads

    const int tid  = threadIdx.x;
    const int row0 = blockIdx.x * BM;
    const int tcol = tid & 15;          // 16 col-groups of TN=8
    const int trow = tid >> 4;          // 16 row-groups of TM=4

    float acc[TM][TN];
#pragma unroll
    for (int i = 0; i < TM; i++)
#pragma unroll
        for (int j = 0; j < TN; j++) acc[i][j] = 0.f;

#pragma unroll
    for (int kc = 0; kc < D; kc += BK) {
        // Load A tile (64 x 32) transposed into As: 512 float4, 2 per thread
#pragma unroll
        for (int i = 0; i < 2; i++) {
            int idx = tid + i * 256;          // 0..511
            int r   = idx >> 3;               // 8 float4 per row
            int c4  = idx & 7;
            float4 v = *reinterpret_cast<const float4*>(
                &emb[(size_t)(row0 + r) * D + kc + c4 * 4]);
            As[c4 * 4 + 0][r] = v.x;
            As[c4 * 4 + 1][r] = v.y;
            As[c4 * 4 + 2][r] = v.z;
            As[c4 * 4 + 3][r] = v.w;
        }
        // Load W tile (32 x 128): 1024 float4, 4 per thread
#pragma unroll
        for (int i = 0; i < 4; i++) {
            int idx = tid + i * 256;          // 0..1023
            int r   = idx >> 5;               // 32 float4 per row
            int c4  = idx & 31;
            float4 v = *reinterpret_cast<const float4*>(
                &W[(size_t)(kc + r) * D + c4 * 4]);
            *reinterpret_cast<float4*>(&Ws[r][c4 * 4]) = v;
        }
        __syncthreads();

#pragma unroll
        for (int k = 0; k < BK; k++) {
            float ra[TM], rb[TN];
#pragma unroll
            for (int i = 0; i < TM; i++) ra[i] = As[k][trow * TM + i];
#pragma unroll
            for (int j = 0; j < TN; j += 4) {
                float4 v = *reinterpret_cast<const float4*>(&Ws[k][tcol * TN + j]);
                rb[j + 0] = v.x; rb[j + 1] = v.y; rb[j + 2] = v.z; rb[j + 3] = v.w;
            }
#pragma unroll
            for (int i = 0; i < TM; i++)
#pragma unroll
                for (int j = 0; j < TN; j++)
                    acc[i][j] = fmaf(ra[i], rb[j], acc[i][j]);
        }
        __syncthreads();
    }

    // Epilogue: +bias, relu, store
#pragma unroll
    for (int i = 0; i < TM; i++) {
        int r = row0 + trow * TM + i;
#pragma unroll
        for (int j = 0; j < TN; j += 4) {
            int c = tcol * TN + j;
            float4 v;
            v.x = fmaxf(acc[i][j + 0] + __ldg(&Bv[c + 0]), 0.f);
            v.y = fmaxf(acc[i][j + 1] + __ldg(&Bv[c + 1]), 0.f);
            v.z = fmaxf(acc[i][j + 2] + __ldg(&Bv[c + 2]), 0.f);
            v.w = fmaxf(acc[i][j + 3] + __ldg(&Bv[c + 3]), 0.f);
            *reinterpret_cast<float4*>(&outT[(size_t)r * D + c]) = v;
        }
    }
}

// ---------------------------------------------------------------------------
// Kernel 3: per-edge message + scatter-sum.
// One warp per edge. Each lane handles 4 contiguous floats (float4).
// msg = T1[node_tokens[src[e]]] * T2[edge_tokens[e]]; vector RED to out[dst[e]].
// ---------------------------------------------------------------------------
__global__ void __launch_bounds__(256) scatter_kernel(
    const int* __restrict__ node_tokens,
    const int* __restrict__ edge_tokens,
    const int* __restrict__ src,
    const int* __restrict__ dst,
    float* __restrict__ out)
{
    int e = blockIdx.x * (blockDim.x >> 5) + (threadIdx.x >> 5);
    if (e >= N_EDGES) return;
    int lane = threadIdx.x & 31;

    int s    = __ldg(&src[e]);
    int d    = __ldg(&dst[e]);
    int tok1 = __ldg(&node_tokens[s]);
    int tok2 = __ldg(&edge_tokens[e]);

    const float4 a = *reinterpret_cast<const float4*>(&g_T1[(size_t)tok1 * D + lane * 4]);
    const float4 b = *reinterpret_cast<const float4*>(&g_T2[(size_t)tok2 * D + lane * 4]);

    float4 m;
    m.x = a.x * b.x; m.y = a.y * b.y; m.z = a.z * b.z; m.w = a.w * b.w;

    float* p = out + (size_t)d * D + lane * 4;   // always 16B-aligned
    asm volatile("red.relaxed.gpu.global.add.v4.f32 [%0], {%1, %2, %3, %4};"
                 :: "l"(p), "f"(m.x), "f"(m.y), "f"(m.z), "f"(m.w)
                 : "memory");
}

// ---------------------------------------------------------------------------
// Launch
// ---------------------------------------------------------------------------
extern "C" void kernel_launch(void* const* d_in, const int* in_sizes, int n_in,
                              void* d_out, int out_size) {
    const float* emb         = (const float*)d_in[0];
    const float* w1          = (const float*)d_in[1];
    const float* b1          = (const float*)d_in[2];
    const float* w2          = (const float*)d_in[3];
    const float* b2          = (const float*)d_in[4];
    const int*   node_tokens = (const int*)d_in[5];
    const int*   edge_tokens = (const int*)d_in[6];
    const int*   src         = (const int*)d_in[7];
    const int*   dst         = (const int*)d_in[8];
    float*       out         = (float*)d_out;

    // Zero output (N_NODES * D floats = 1.6M float4)
    int n4 = N_NODES * D / 4;
    zero_kernel<<<(n4 + 255) / 256, 256>>>((float4*)out, n4);

    // Per-token transformed embeddings: two GEMMs in one launch (blockIdx.y)
    dim3 ggrid(VOCAB / BM, 2);
    gemm_relu_kernel<<<ggrid, 256>>>(emb, w1, b1, w2, b2);

    // Edge scatter: 1 warp per edge, 8 warps per block
    int nblocks = (N_EDGES + 7) / 8;
    scatter_kernel<<<nblocks, 256>>>(node_tokens, edge_tokens, src, dst, out);
}